// round 2
// baseline (speedup 1.0000x reference)
#include <cuda_runtime.h>
#include <math.h>

// Problem constants
#define S_ 512      // sequences per stage (B*T or B*F)
#define L_ 128      // sequence length
#define CH 64       // d_model
#define DI 128      // d_inner
#define DIP 386     // d_in_proj
#define CONVD 256   // conv channels

// ---- scratch (static device globals; no runtime allocation) ----
__device__ float g_xwork[(size_t)4*64*128*128];          // 16.8 MB residual stream
__device__ float g_u[(size_t)S_*L_*CH];                  // layernormed sequences
__device__ float g_zx[2][(size_t)S_*L_*DIP];             // in_proj output per direction
__device__ float g_gbuf[(size_t)S_*L_*256];              // gated+rmsnormed [fwd|bwd]
__device__ float g_wc[64*256];                           // folded out_proj x fusion weights

// ============================================================
// LayerNorm over channel dim + layout to (seq, pos, ch)
// block = one (b, t) slice of 64 x 128 (c, f)
// ============================================================
__global__ void ln_kernel(const float* __restrict__ x_ext,
                          const float* __restrict__ lnw, const float* __restrict__ lnb,
                          int stage)
{
    __shared__ float tile[64][133];
    __shared__ float msh[128], rsh[128], wsh[64], bsh[64];
    const float* xin = stage ? g_xwork : x_ext;
    int bt = blockIdx.x, b = bt >> 7, t = bt & 127;
    int tid = threadIdx.x;
    if (tid < 64) { wsh[tid] = lnw[tid]; bsh[tid] = lnb[tid]; }
    const float* xb = xin + ((size_t)b*64*128 + t)*128;   // x[b, c, t, f]
    for (int i = tid; i < 8192; i += 256) {
        int c = i >> 7, f = i & 127;
        tile[c][f] = xb[(size_t)c*16384 + f];
    }
    __syncthreads();
    if (tid < 128) {
        float s = 0.f, ss = 0.f;
        #pragma unroll
        for (int c = 0; c < 64; c++) { float v = tile[c][tid]; s += v; ss += v*v; }
        float m = s * 0.015625f;
        msh[tid] = m;
        rsh[tid] = rsqrtf(ss * 0.015625f - m*m + 1e-5f);
    }
    __syncthreads();
    for (int i = tid; i < 8192; i += 256) {
        int f = i >> 6, c = i & 63;
        int row = stage ? ((b << 7) + f)*128 + t : ((b << 7) + t)*128 + f;
        g_u[(size_t)row*64 + c] = (tile[c][f] - msh[f]) * rsh[f] * wsh[c] + bsh[c];
    }
}

// ============================================================
// in_proj GEMM: g_zx[dir][r, n] = sum_k g_u[r,k] * W[n,k]
// M=65536, N=386, K=64. 64x64 tiles, 4x4 per thread.
// ============================================================
__global__ __launch_bounds__(256) void gemm_inproj(const float* __restrict__ W, int dir)
{
    __shared__ float As[16][68];
    __shared__ float Ws[16][68];
    float* Cout = g_zx[dir];
    int bn = blockIdx.x * 64;
    size_t bm = (size_t)blockIdx.y * 64;
    int tid = threadIdx.x, tr = tid >> 4, tc = tid & 15;
    float acc[4][4] = {};
    #pragma unroll
    for (int k0 = 0; k0 < 64; k0 += 16) {
        #pragma unroll
        for (int i = tid; i < 1024; i += 256) {
            int m = i >> 4, k = i & 15;
            As[k][m] = g_u[(bm + m)*64 + k0 + k];
        }
        #pragma unroll
        for (int i = tid; i < 1024; i += 256) {
            int n = i >> 4, k = i & 15;
            int nn = bn + n;
            Ws[k][n] = (nn < 386) ? W[(size_t)nn*64 + k0 + k] : 0.f;
        }
        __syncthreads();
        #pragma unroll
        for (int k = 0; k < 16; k++) {
            float a[4], b4[4];
            *(float4*)a  = *(const float4*)&As[k][tr*4];
            *(float4*)b4 = *(const float4*)&Ws[k][tc*4];
            #pragma unroll
            for (int ii = 0; ii < 4; ii++)
                #pragma unroll
                for (int jj = 0; jj < 4; jj++)
                    acc[ii][jj] = fmaf(a[ii], b4[jj], acc[ii][jj]);
        }
        __syncthreads();
    }
    #pragma unroll
    for (int ii = 0; ii < 4; ii++) {
        size_t m = bm + tr*4 + ii;
        #pragma unroll
        for (int jj = 0; jj < 4; jj++) {
            int n = bn + tc*4 + jj;
            if (n < 386) Cout[m*386 + n] = acc[ii][jj];
        }
    }
}

// ============================================================
// Fused conv(k=4,causal)+silu + selective scan + gate + rmsnorm.
// One block per (seq, dir). 128 threads = (head, p). h[64] in regs.
// ============================================================
__global__ __launch_bounds__(128, 4) void scan_kernel(
    const float* __restrict__ convW, const float* __restrict__ convB,
    const float* __restrict__ dtbias, const float* __restrict__ Alog,
    const float* __restrict__ Dparam, const float* __restrict__ normw,
    int pf, int pb)
{
    __shared__ float ring[4][256];
    __shared__ float xact[256];
    __shared__ float zsh[128];
    __shared__ float cwsh[4][256];
    __shared__ float cbsh[256];
    __shared__ float dsh[4];       // [dt0, dt1, dA0, dA1]
    __shared__ float red[4];
    __shared__ float dtb2[2], negA2[2];

    int blk = blockIdx.x, dir = blk >> 9, s = blk & 511;
    int pidx = dir ? pb : pf;
    int tid = threadIdx.x, head = tid >> 6;
    const float* zx = g_zx[dir] + (size_t)s * L_ * DIP;

    for (int i = tid; i < 1024; i += 128) {
        int j = i & 255, k = i >> 8;
        cwsh[k][j] = convW[pidx*1024 + j*4 + k];
        ((float*)ring)[i] = 0.f;
    }
    for (int i = tid; i < 256; i += 128) cbsh[i] = convB[pidx*256 + i];
    if (tid < 2) {
        dtb2[tid]  = dtbias[pidx*2 + tid];
        negA2[tid] = -expf(Alog[pidx*2 + tid]);
    }
    float nwv = normw[pidx*128 + tid];
    float Dv  = Dparam[pidx*2 + head];
    float h[64];
    #pragma unroll
    for (int n = 0; n < 64; n++) h[n] = 0.f;
    __syncthreads();

    for (int l = 0; l < 128; l++) {
        int lp = dir ? 127 - l : l;                 // physical position
        const float* row = zx + (size_t)lp * DIP;
        // cooperative load: z (0:128), xBC (128:384) into ring, dt raw (384:386)
        zsh[tid] = row[tid];
        int slot = l & 3;
        ring[slot][tid]       = row[128 + tid];
        ring[slot][128 + tid] = row[256 + tid];
        if (tid < 2) {
            float xr = row[384 + tid] + dtb2[tid];
            float dt = (xr > 20.f) ? xr : log1pf(expf(xr));
            dsh[tid]     = dt;
            dsh[2 + tid] = expf(negA2[tid] * dt);
        }
        __syncthreads();
        // depthwise causal conv + silu (2 channels / thread)
        #pragma unroll
        for (int jj = 0; jj < 2; jj++) {
            int j = tid + (jj << 7);
            float acc = cbsh[j];
            #pragma unroll
            for (int k = 0; k < 4; k++)
                acc = fmaf(cwsh[k][j], ring[(l - 3 + k) & 3][j], acc);
            xact[j] = acc / (1.f + expf(-acc));
        }
        __syncthreads();
        // scan update + output
        float dA  = dsh[2 + head];
        float xv  = xact[tid];
        float dtx = dsh[head] * xv;
        float y0 = 0.f, y1 = 0.f, y2 = 0.f, y3 = 0.f;
        #pragma unroll
        for (int n = 0; n < 64; n += 4) {
            h[n]   = fmaf(h[n],   dA, dtx * xact[128 + n]);
            h[n+1] = fmaf(h[n+1], dA, dtx * xact[129 + n]);
            h[n+2] = fmaf(h[n+2], dA, dtx * xact[130 + n]);
            h[n+3] = fmaf(h[n+3], dA, dtx * xact[131 + n]);
            y0 = fmaf(h[n],   xact[192 + n], y0);
            y1 = fmaf(h[n+1], xact[193 + n], y1);
            y2 = fmaf(h[n+2], xact[194 + n], y2);
            y3 = fmaf(h[n+3], xact[195 + n], y3);
        }
        float y  = (y0 + y1) + (y2 + y3) + Dv * xv;
        float zv = zsh[tid];
        float g  = y * (zv / (1.f + expf(-zv)));
        // rmsnorm over 128 channels
        float sq = g * g;
        #pragma unroll
        for (int o = 16; o > 0; o >>= 1) sq += __shfl_xor_sync(0xffffffffu, sq, o);
        if ((tid & 31) == 0) red[tid >> 5] = sq;
        __syncthreads();
        float rs = rsqrtf((red[0] + red[1] + red[2] + red[3]) * 0.0078125f + 1e-5f);
        g_gbuf[((size_t)s*128 + lp)*256 + (dir << 7) + tid] = g * rs * nwv;
        __syncthreads();
    }
}

// ============================================================
// Fold out_proj + fusion: g_wc[m, dir*128+j] = sum_i Wf[m, dir*64+i] * Wo[i, j]
// ============================================================
__global__ void wc_kernel(const float* __restrict__ fW, const float* __restrict__ oW,
                          int pf, int pb)
{
    int idx = blockIdx.x*256 + threadIdx.x;          // 64*256 outputs
    int m = idx >> 8, r = idx & 255, dir = r >> 7, j = r & 127;
    int pidx = dir ? pb : pf;
    const float* wo = oW + (size_t)pidx*64*128;
    const float* wf = fW + m*128 + (dir << 6);
    float acc = 0.f;
    #pragma unroll
    for (int i = 0; i < 64; i++) acc = fmaf(wf[i], wo[i*128 + j], acc);
    g_wc[idx] = acc;
}

// ============================================================
// final GEMM: out[r, c] = gbuf[r, :256] . g_wc[c, :256] + fb[c], + residual,
// scattered back into (b, c, t, f) layout. M=65536, N=64, K=256.
// ============================================================
__global__ __launch_bounds__(256) void gemm_out(const float* __restrict__ fb,
        const float* __restrict__ x_ext, float* __restrict__ out_ext, int stage)
{
    __shared__ float As[16][68];
    __shared__ float Ws[16][68];
    const float* xin = stage ? g_xwork : x_ext;
    float* xout = stage ? out_ext : g_xwork;
    size_t bm = (size_t)blockIdx.x * 64;
    int tid = threadIdx.x, tr = tid >> 4, tc = tid & 15;
    float acc[4][4] = {};
    for (int k0 = 0; k0 < 256; k0 += 16) {
        #pragma unroll
        for (int i = tid; i < 1024; i += 256) {
            int m = i >> 4, k = i & 15;
            As[k][m] = g_gbuf[(bm + m)*256 + k0 + k];
        }
        #pragma unroll
        for (int i = tid; i < 1024; i += 256) {
            int n = i >> 4, k = i & 15;
            Ws[k][n] = g_wc[n*256 + k0 + k];
        }
        __syncthreads();
        #pragma unroll
        for (int k = 0; k < 16; k++) {
            float a[4], b4[4];
            *(float4*)a  = *(const float4*)&As[k][tr*4];
            *(float4*)b4 = *(const float4*)&Ws[k][tc*4];
            #pragma unroll
            for (int ii = 0; ii < 4; ii++)
                #pragma unroll
                for (int jj = 0; jj < 4; jj++)
                    acc[ii][jj] = fmaf(a[ii], b4[jj], acc[ii][jj]);
        }
        __syncthreads();
    }
    #pragma unroll
    for (int ii = 0; ii < 4; ii++) {
        size_t r = bm + tr*4 + ii;
        int b = (int)(r >> 14), low = (int)(r & 16383);
        int t_, f_;
        if (stage == 0) { t_ = low >> 7; f_ = low & 127; }
        else            { f_ = low >> 7; t_ = low & 127; }
        #pragma unroll
        for (int jj = 0; jj < 4; jj++) {
            int n = tc*4 + jj;
            size_t idx = (((size_t)(b*64 + n)*128) + t_)*128 + f_;
            xout[idx] = xin[idx] + acc[ii][jj] + fb[n];
        }
    }
}

// ============================================================
extern "C" void kernel_launch(void* const* d_in, const int* in_sizes, int n_in,
                              void* d_out, int out_size)
{
    const float* x     = (const float*)d_in[0];
    const float* inW   = (const float*)d_in[1];
    const float* convW = (const float*)d_in[2];
    const float* convB = (const float*)d_in[3];
    const float* dtb   = (const float*)d_in[4];
    const float* Alog  = (const float*)d_in[5];
    const float* Dp    = (const float*)d_in[6];
    const float* nw    = (const float*)d_in[7];
    const float* outW  = (const float*)d_in[8];
    const float* fW    = (const float*)d_in[9];
    const float* fb    = (const float*)d_in[10];
    const float* lnw   = (const float*)d_in[11];
    const float* lnb   = (const float*)d_in[12];
    float* out = (float*)d_out;

    for (int st = 0; st < 2; st++) {
        int pf = 2*st, pb = 2*st + 1;
        ln_kernel<<<512, 256>>>(x, lnw + st*64, lnb + st*64, st);
        gemm_inproj<<<dim3(7, 1024), 256>>>(inW + (size_t)pf*386*64, 0);
        gemm_inproj<<<dim3(7, 1024), 256>>>(inW + (size_t)pb*386*64, 1);
        scan_kernel<<<1024, 128>>>(convW, convB, dtb, Alog, Dp, nw, pf, pb);
        wc_kernel<<<64, 256>>>(fW + st*64*128, outW, pf, pb);
        gemm_out<<<1024, 256>>>(fb + st*64, x, out, st);
    }
}

// round 3
// speedup vs baseline: 1.0280x; 1.0280x over previous
#include <cuda_runtime.h>
#include <math.h>

// Problem constants
#define S_ 512      // sequences per stage
#define L_ 128      // sequence length
#define CH 64       // d_model

// ---- packed f32x2 helpers (Blackwell FFMA2 path) ----
__device__ __forceinline__ float2 ffma2(float2 a, float2 b, float2 c) {
    unsigned long long ua = *reinterpret_cast<unsigned long long*>(&a);
    unsigned long long ub = *reinterpret_cast<unsigned long long*>(&b);
    unsigned long long uc = *reinterpret_cast<unsigned long long*>(&c);
    unsigned long long ud;
    asm("fma.rn.f32x2 %0, %1, %2, %3;" : "=l"(ud) : "l"(ua), "l"(ub), "l"(uc));
    return *reinterpret_cast<float2*>(&ud);
}
__device__ __forceinline__ float2 fmul2(float2 a, float2 b) {
    unsigned long long ua = *reinterpret_cast<unsigned long long*>(&a);
    unsigned long long ub = *reinterpret_cast<unsigned long long*>(&b);
    unsigned long long ud;
    asm("mul.rn.f32x2 %0, %1, %2;" : "=l"(ud) : "l"(ua), "l"(ub));
    return *reinterpret_cast<float2*>(&ud);
}

// ---- scratch (static device globals) ----
__device__ __align__(16) float g_xwork[(size_t)4*64*128*128];   // residual stream
__device__ __align__(16) float g_u[(size_t)S_*L_*CH];           // layernormed rows
__device__ __align__(16) float g_zx[2][(size_t)S_*L_*384];      // z|xBC per direction
__device__ __align__(16) float g_dt[2][(size_t)S_*L_*4];        // {dt0,dt1,dA0,dA1}
__device__ __align__(16) float g_gbuf[(size_t)S_*L_*256];       // gated+rmsnormed
__device__ __align__(16) float g_wc[64*256];                    // folded out weights

// ============================================================
// LayerNorm over channels + layout to (seq, pos, ch)
// ============================================================
__global__ void ln_kernel(const float* __restrict__ x_ext,
                          const float* __restrict__ lnw, const float* __restrict__ lnb,
                          int stage)
{
    __shared__ float tile[64][133];
    __shared__ float msh[128], rsh[128], wsh[64], bsh[64];
    const float* xin = stage ? g_xwork : x_ext;
    int bt = blockIdx.x, b = bt >> 7, t = bt & 127;
    int tid = threadIdx.x;
    if (tid < 64) { wsh[tid] = lnw[tid]; bsh[tid] = lnb[tid]; }
    const float* xb = xin + ((size_t)b*64*128 + t)*128;
    for (int i = tid; i < 8192; i += 256) {
        int c = i >> 7, f = i & 127;
        tile[c][f] = xb[(size_t)c*16384 + f];
    }
    __syncthreads();
    if (tid < 128) {
        float s = 0.f, ss = 0.f;
        #pragma unroll
        for (int c = 0; c < 64; c++) { float v = tile[c][tid]; s += v; ss += v*v; }
        float m = s * 0.015625f;
        msh[tid] = m;
        rsh[tid] = rsqrtf(ss * 0.015625f - m*m + 1e-5f);
    }
    __syncthreads();
    for (int i = tid; i < 8192; i += 256) {
        int f = i >> 6, c = i & 63;
        int row = stage ? ((b << 7) + f)*128 + t : ((b << 7) + t)*128 + f;
        g_u[(size_t)row*64 + c] = (tile[c][f] - msh[f]) * rsh[f] * wsh[c] + bsh[c];
    }
}

// ============================================================
// Combined in_proj GEMM for both directions.
// C[m, n] = u[m,:] . W[n,:],  M=65536, N=768 (2 dirs x 384), K=64.
// 128x128 tiles, 8x8 per thread, FFMA2 with duplicated-A smem.
// ============================================================
#define GKC 16
__global__ __launch_bounds__(256, 2) void gemm_in(const float* __restrict__ Wf,
                                                  const float* __restrict__ Wb)
{
    __shared__ __align__(16) float As2[GKC][264];  // duplicated A: [k][2m,2m+1]
    __shared__ __align__(16) float Bs[GKC][132];
    int bx = blockIdx.x;                   // 0..5
    int dir = (bx >= 3);
    const float* W = dir ? Wb : Wf;
    int j0 = (bx - dir*3) * 128;           // W row block (0..383)
    size_t bm = (size_t)blockIdx.y * 128;
    int tid = threadIdx.x;
    int tr = tid >> 4, tc = tid & 15;
    float2 acc[8][4];
    #pragma unroll
    for (int i = 0; i < 8; i++)
        #pragma unroll
        for (int j = 0; j < 4; j++) acc[i][j] = make_float2(0.f, 0.f);

    for (int k0 = 0; k0 < 64; k0 += GKC) {
        // load A tile 128m x 16k (duplicated)
        #pragma unroll
        for (int t = 0; t < 2; t++) {
            int i = tid + t*256;           // 0..511
            int m = i >> 2, kg = (i & 3) * 4;
            float4 v = *(const float4*)&g_u[(bm + m)*64 + k0 + kg];
            *(float2*)&As2[kg+0][2*m] = make_float2(v.x, v.x);
            *(float2*)&As2[kg+1][2*m] = make_float2(v.y, v.y);
            *(float2*)&As2[kg+2][2*m] = make_float2(v.z, v.z);
            *(float2*)&As2[kg+3][2*m] = make_float2(v.w, v.w);
        }
        // load B tile 16k x 128n
        #pragma unroll
        for (int t = 0; t < 2; t++) {
            int i = tid + t*256;
            int n = i >> 2, kg = (i & 3) * 4;
            float4 v = *(const float4*)&W[(size_t)(j0 + n)*64 + k0 + kg];
            Bs[kg+0][n] = v.x; Bs[kg+1][n] = v.y; Bs[kg+2][n] = v.z; Bs[kg+3][n] = v.w;
        }
        __syncthreads();
        #pragma unroll
        for (int k = 0; k < GKC; k++) {
            float4 a01 = *(const float4*)&As2[k][tr*16];
            float4 a23 = *(const float4*)&As2[k][tr*16 + 4];
            float4 a45 = *(const float4*)&As2[k][tr*16 + 8];
            float4 a67 = *(const float4*)&As2[k][tr*16 + 12];
            float4 b03 = *(const float4*)&Bs[k][tc*8];
            float4 b47 = *(const float4*)&Bs[k][tc*8 + 4];
            float2 a2[8] = { {a01.x,a01.y},{a01.z,a01.w},{a23.x,a23.y},{a23.z,a23.w},
                             {a45.x,a45.y},{a45.z,a45.w},{a67.x,a67.y},{a67.z,a67.w} };
            float2 b2[4] = { {b03.x,b03.y},{b03.z,b03.w},{b47.x,b47.y},{b47.z,b47.w} };
            #pragma unroll
            for (int ii = 0; ii < 8; ii++)
                #pragma unroll
                for (int jj = 0; jj < 4; jj++)
                    acc[ii][jj] = ffma2(a2[ii], b2[jj], acc[ii][jj]);
        }
        __syncthreads();
    }
    float* Cout = g_zx[dir];
    #pragma unroll
    for (int ii = 0; ii < 8; ii++) {
        size_t m = bm + tr*8 + ii;
        float4 o0 = make_float4(acc[ii][0].x, acc[ii][0].y, acc[ii][1].x, acc[ii][1].y);
        float4 o1 = make_float4(acc[ii][2].x, acc[ii][2].y, acc[ii][3].x, acc[ii][3].y);
        *(float4*)&Cout[m*384 + j0 + tc*8]     = o0;
        *(float4*)&Cout[m*384 + j0 + tc*8 + 4] = o1;
    }
}

// ============================================================
// dt precompute: g_dt[dir][r] = {dt0, dt1, dA0, dA1}
// dt = softplus(u[r].W[384+h] + bias), dA = exp(-exp(Alog)*dt)
// ============================================================
__global__ __launch_bounds__(256) void dt_kernel(const float* __restrict__ inW,
        const float* __restrict__ dtb, const float* __restrict__ Alog, int pf, int pb)
{
    __shared__ float usm[128][65];
    __shared__ float wsm[2][2][64];
    __shared__ float par[2][2][2];   // [dir][h][{bias, negA}]
    int tid = threadIdx.x;
    int r0 = blockIdx.x * 128;
    for (int i = tid; i < 8192; i += 256) {
        int m = i >> 6, k = i & 63;
        usm[m][k] = g_u[(size_t)(r0 + m)*64 + k];
    }
    if (tid < 256) {
        int d = tid >> 7, rest = tid & 127, h = rest >> 6, k = rest & 63;
        int pidx = d ? pb : pf;
        wsm[d][h][k] = inW[(size_t)pidx*386*64 + (384 + h)*64 + k];
    }
    if (tid < 4) {
        int d = tid >> 1, h = tid & 1;
        int pidx = d ? pb : pf;
        par[d][h][0] = dtb[pidx*2 + h];
        par[d][h][1] = -expf(Alog[pidx*2 + h]);
    }
    __syncthreads();
    int rl = tid & 127, d = tid >> 7;
    float out[4];
    #pragma unroll
    for (int h = 0; h < 2; h++) {
        float acc = 0.f;
        #pragma unroll
        for (int k = 0; k < 64; k++) acc = fmaf(usm[rl][k], wsm[d][h][k], acc);
        float xr = acc + par[d][h][0];
        float dt = (xr > 20.f) ? xr : log1pf(expf(xr));
        out[h] = dt;
        out[2 + h] = expf(par[d][h][1] * dt);
    }
    float* o = &g_dt[d][(size_t)(r0 + rl)*4];
    o[0] = out[0]; o[1] = out[1]; o[2] = out[2]; o[3] = out[3];
}

// ============================================================
// Fused conv(k=4)+silu + scan + gate + rmsnorm, batched x4 steps.
// 256 threads: head = tid>>7, p = (tid>>1)&63, nh = tid&1 (32 states each).
// ============================================================
__global__ __launch_bounds__(256, 2) void scan_kernel(
    const float* __restrict__ convW, const float* __restrict__ convB,
    const float* __restrict__ Dparam, const float* __restrict__ normw,
    int pf, int pb)
{
    __shared__ __align__(16) float ring[8][256];
    __shared__ __align__(16) float xact[4][256];
    __shared__ float zsh[4][128];
    __shared__ float cwsh[4][256];
    __shared__ float cbsh[256];
    __shared__ float dsh[4][4];
    __shared__ float red[4][8];

    int blk = blockIdx.x, dir = blk >> 9, s = blk & 511;
    int pidx = dir ? pb : pf;
    int tid = threadIdx.x;
    int head = tid >> 7, p = (tid >> 1) & 63, nh = tid & 1;
    int ch = head*64 + p;
    int n0 = nh * 32;
    const float* zxbase = g_zx[dir] + (size_t)s * L_ * 384;
    const float* dtbase = g_dt[dir] + (size_t)s * L_ * 4;
    float* gout = g_gbuf + (size_t)s * L_ * 256 + (dir << 7);

    for (int i = tid; i < 1024; i += 256) {
        int k = i >> 8, j = i & 255;
        cwsh[k][j] = convW[pidx*1024 + j*4 + k];
    }
    cbsh[tid] = convB[pidx*256 + tid];
    for (int i = tid; i < 2048; i += 256) ((float*)ring)[i] = 0.f;
    float nwv = normw[pidx*128 + ch];
    float Dv  = Dparam[pidx*2 + head];
    float2 h2[16];
    #pragma unroll
    for (int k = 0; k < 16; k++) h2[k] = make_float2(0.f, 0.f);
    __syncthreads();

    for (int l0 = 0; l0 < 128; l0 += 4) {
        // ---- load 4 rows ----
        #pragma unroll
        for (int st = 0; st < 4; st++) {
            int lp = dir ? (127 - (l0 + st)) : (l0 + st);
            const float* row = zxbase + (size_t)lp * 384;
            int slot = (l0 + st) & 7;
            float v = row[tid];
            if (tid < 128) zsh[st][tid] = v; else ring[slot][tid - 128] = v;
            if (tid < 128) ring[slot][128 + tid] = row[256 + tid];
        }
        if (tid < 16) {
            int st = tid >> 2, q = tid & 3;
            int lp = dir ? (127 - (l0 + st)) : (l0 + st);
            dsh[st][q] = dtbase[(size_t)lp*4 + q];
        }
        __syncthreads();
        // ---- conv + silu for 4 steps (1 channel / thread) ----
        #pragma unroll
        for (int st = 0; st < 4; st++) {
            float acc = cbsh[tid];
            #pragma unroll
            for (int k = 0; k < 4; k++)
                acc = fmaf(cwsh[k][tid], ring[(l0 + st - 3 + k) & 7][tid], acc);
            xact[st][tid] = acc / (1.f + expf(-acc));
        }
        __syncthreads();
        // ---- scan 4 steps ----
        float gv[4], sqv[4];
        #pragma unroll
        for (int st = 0; st < 4; st++) {
            float dt_h = dsh[st][head], dAv = dsh[st][2 + head];
            float xv = xact[st][ch];
            float dtx = dt_h * xv;
            float2 dA2  = make_float2(dAv, dAv);
            float2 dtx2 = make_float2(dtx, dtx);
            const float2* Bp = (const float2*)&xact[st][128 + n0];
            const float2* Cp = (const float2*)&xact[st][192 + n0];
            float2 y2 = make_float2(0.f, 0.f);
            #pragma unroll
            for (int k = 0; k < 16; k++) {
                float2 t = fmul2(dtx2, Bp[k]);
                h2[k] = ffma2(h2[k], dA2, t);
                y2 = ffma2(h2[k], Cp[k], y2);
            }
            float y = y2.x + y2.y;
            y += __shfl_xor_sync(0xffffffffu, y, 1);
            y = fmaf(Dv, xv, y);
            float zv = zsh[st][ch];
            float g = y * (zv / (1.f + expf(-zv)));
            gv[st] = g;
            float sq = g * g;
            #pragma unroll
            for (int o = 16; o; o >>= 1) sq += __shfl_xor_sync(0xffffffffu, sq, o);
            sqv[st] = sq;     // = 2 x sum over this warp's 16 channels
        }
        if ((tid & 31) == 0) {
            int w = tid >> 5;
            red[0][w] = sqv[0]; red[1][w] = sqv[1];
            red[2][w] = sqv[2]; red[3][w] = sqv[3];
        }
        __syncthreads();
        if (nh == 0) {
            #pragma unroll
            for (int st = 0; st < 4; st++) {
                float tot = ((red[st][0] + red[st][1]) + (red[st][2] + red[st][3]))
                          + ((red[st][4] + red[st][5]) + (red[st][6] + red[st][7]));
                float rs = rsqrtf(tot * 0.00390625f + 1e-5f);   // /(2*128)
                int lp = dir ? (127 - (l0 + st)) : (l0 + st);
                gout[(size_t)lp*256 + ch] = gv[st] * rs * nwv;
            }
        }
        // no trailing barrier needed: next load-phase writes are ordered by
        // the next __syncthreads before any reader touches them.
    }
}

// ============================================================
// Fold out_proj x fusion: g_wc[m, dir*128+j]
// ============================================================
__global__ void wc_kernel(const float* __restrict__ fW, const float* __restrict__ oW,
                          int pf, int pb)
{
    int idx = blockIdx.x*256 + threadIdx.x;
    int m = idx >> 8, r = idx & 255, dir = r >> 7, j = r & 127;
    int pidx = dir ? pb : pf;
    const float* wo = oW + (size_t)pidx*64*128;
    const float* wf = fW + m*128 + (dir << 6);
    float acc = 0.f;
    #pragma unroll
    for (int i = 0; i < 64; i++) acc = fmaf(wf[i], wo[i*128 + j], acc);
    g_wc[idx] = acc;
}

// ============================================================
// final GEMM + residual + scatter. M=65536, N=64, K=256.
// ============================================================
__global__ __launch_bounds__(256) void gemm_out(const float* __restrict__ fb,
        const float* __restrict__ x_ext, float* __restrict__ out_ext, int stage)
{
    __shared__ __align__(16) float As[16][68];
    __shared__ __align__(16) float Ws[16][68];
    const float* xin = stage ? g_xwork : x_ext;
    float* xout = stage ? out_ext : g_xwork;
    size_t bm = (size_t)blockIdx.x * 64;
    int tid = threadIdx.x, tr = tid >> 4, tc = tid & 15;
    float acc[4][4] = {};
    for (int k0 = 0; k0 < 256; k0 += 16) {
        #pragma unroll
        for (int i = tid; i < 1024; i += 256) {
            int m = i >> 4, k = i & 15;
            As[k][m] = g_gbuf[(bm + m)*256 + k0 + k];
        }
        #pragma unroll
        for (int i = tid; i < 1024; i += 256) {
            int n = i >> 4, k = i & 15;
            Ws[k][n] = g_wc[n*256 + k0 + k];
        }
        __syncthreads();
        #pragma unroll
        for (int k = 0; k < 16; k++) {
            float a[4], b4[4];
            *(float4*)a  = *(const float4*)&As[k][tr*4];
            *(float4*)b4 = *(const float4*)&Ws[k][tc*4];
            #pragma unroll
            for (int ii = 0; ii < 4; ii++)
                #pragma unroll
                for (int jj = 0; jj < 4; jj++)
                    acc[ii][jj] = fmaf(a[ii], b4[jj], acc[ii][jj]);
        }
        __syncthreads();
    }
    #pragma unroll
    for (int ii = 0; ii < 4; ii++) {
        size_t r = bm + tr*4 + ii;
        int b = (int)(r >> 14), low = (int)(r & 16383);
        int t_, f_;
        if (stage == 0) { t_ = low >> 7; f_ = low & 127; }
        else            { f_ = low >> 7; t_ = low & 127; }
        #pragma unroll
        for (int jj = 0; jj < 4; jj++) {
            int n = tc*4 + jj;
            size_t idx = (((size_t)(b*64 + n)*128) + t_)*128 + f_;
            xout[idx] = xin[idx] + acc[ii][jj] + fb[n];
        }
    }
}

// ============================================================
extern "C" void kernel_launch(void* const* d_in, const int* in_sizes, int n_in,
                              void* d_out, int out_size)
{
    const float* x     = (const float*)d_in[0];
    const float* inW   = (const float*)d_in[1];
    const float* convW = (const float*)d_in[2];
    const float* convB = (const float*)d_in[3];
    const float* dtb   = (const float*)d_in[4];
    const float* Alog  = (const float*)d_in[5];
    const float* Dp    = (const float*)d_in[6];
    const float* nw    = (const float*)d_in[7];
    const float* outW  = (const float*)d_in[8];
    const float* fW    = (const float*)d_in[9];
    const float* fb    = (const float*)d_in[10];
    const float* lnw   = (const float*)d_in[11];
    const float* lnb   = (const float*)d_in[12];
    float* out = (float*)d_out;

    for (int st = 0; st < 2; st++) {
        int pf = 2*st, pb = 2*st + 1;
        ln_kernel<<<512, 256>>>(x, lnw + st*64, lnb + st*64, st);
        gemm_in<<<dim3(6, 512), 256>>>(inW + (size_t)pf*386*64, inW + (size_t)pb*386*64);
        dt_kernel<<<512, 256>>>(inW, dtb, Alog, pf, pb);
        scan_kernel<<<1024, 256>>>(convW, convB, Dp, nw, pf, pb);
        wc_kernel<<<64, 256>>>(fW + st*64*128, outW, pf, pb);
        gemm_out<<<1024, 256>>>(fb + st*64, x, out, st);
    }
}

// round 4
// speedup vs baseline: 1.1522x; 1.1209x over previous
#include <cuda_runtime.h>
#include <math.h>

#define S_ 512
#define L_ 128

// ---- packed f32x2 helpers ----
__device__ __forceinline__ float2 ffma2(float2 a, float2 b, float2 c) {
    unsigned long long ua = *reinterpret_cast<unsigned long long*>(&a);
    unsigned long long ub = *reinterpret_cast<unsigned long long*>(&b);
    unsigned long long uc = *reinterpret_cast<unsigned long long*>(&c);
    unsigned long long ud;
    asm("fma.rn.f32x2 %0, %1, %2, %3;" : "=l"(ud) : "l"(ua), "l"(ub), "l"(uc));
    return *reinterpret_cast<float2*>(&ud);
}
__device__ __forceinline__ float2 dup2(float a) {
    unsigned long long u;
    asm("mov.b64 %0, {%1, %1};" : "=l"(u) : "f"(a));
    return *reinterpret_cast<float2*>(&u);
}

// ---- scratch ----
__device__ __align__(16) float g_xwork[(size_t)4*64*128*128];
__device__ __align__(16) float g_u[(size_t)S_*L_*64];
__device__ __align__(16) float g_zx[2][(size_t)S_*L_*384];   // z | xBC (conv in-place)
__device__ __align__(16) float g_dt[2][(size_t)S_*L_*4];     // {dt0,dt1,ldA0,ldA1}
__device__ __align__(16) float g_gbuf[(size_t)S_*L_*256];
__device__ __align__(16) float g_wc[64*256];

// ============================================================
// LayerNorm over channels + layout to (seq, pos, ch)
// ============================================================
__global__ void ln_kernel(const float* __restrict__ x_ext,
                          const float* __restrict__ lnw, const float* __restrict__ lnb,
                          int stage)
{
    __shared__ float tile[64][133];
    __shared__ float msh[128], rsh[128], wsh[64], bsh[64];
    const float* xin = stage ? g_xwork : x_ext;
    int bt = blockIdx.x, b = bt >> 7, t = bt & 127;
    int tid = threadIdx.x;
    if (tid < 64) { wsh[tid] = lnw[tid]; bsh[tid] = lnb[tid]; }
    const float* xb = xin + ((size_t)b*64*128 + t)*128;
    for (int i = tid; i < 8192; i += 256) {
        int c = i >> 7, f = i & 127;
        tile[c][f] = xb[(size_t)c*16384 + f];
    }
    __syncthreads();
    if (tid < 128) {
        float s = 0.f, ss = 0.f;
        #pragma unroll
        for (int c = 0; c < 64; c++) { float v = tile[c][tid]; s += v; ss += v*v; }
        float m = s * 0.015625f;
        msh[tid] = m;
        rsh[tid] = rsqrtf(ss * 0.015625f - m*m + 1e-5f);
    }
    __syncthreads();
    for (int i = tid; i < 8192; i += 256) {
        int f = i >> 6, c = i & 63;
        int row = stage ? ((b << 7) + f)*128 + t : ((b << 7) + t)*128 + f;
        g_u[(size_t)row*64 + c] = (tile[c][f] - msh[f]) * rsh[f] * wsh[c] + bsh[c];
    }
}

// ============================================================
// in_proj GEMM, both directions. M=65536, N=768, K=64.
// ============================================================
#define GKC 16
__global__ __launch_bounds__(256, 2) void gemm_in(const float* __restrict__ Wf,
                                                  const float* __restrict__ Wb)
{
    __shared__ __align__(16) float As2[GKC][264];
    __shared__ __align__(16) float Bs[GKC][132];
    int bx = blockIdx.x;
    int dir = (bx >= 3);
    const float* W = dir ? Wb : Wf;
    int j0 = (bx - dir*3) * 128;
    size_t bm = (size_t)blockIdx.y * 128;
    int tid = threadIdx.x;
    int tr = tid >> 4, tc = tid & 15;
    float2 acc[8][4];
    #pragma unroll
    for (int i = 0; i < 8; i++)
        #pragma unroll
        for (int j = 0; j < 4; j++) acc[i][j] = make_float2(0.f, 0.f);

    for (int k0 = 0; k0 < 64; k0 += GKC) {
        #pragma unroll
        for (int t = 0; t < 2; t++) {
            int i = tid + t*256;
            int m = i >> 2, kg = (i & 3) * 4;
            float4 v = *(const float4*)&g_u[(bm + m)*64 + k0 + kg];
            *(float2*)&As2[kg+0][2*m] = make_float2(v.x, v.x);
            *(float2*)&As2[kg+1][2*m] = make_float2(v.y, v.y);
            *(float2*)&As2[kg+2][2*m] = make_float2(v.z, v.z);
            *(float2*)&As2[kg+3][2*m] = make_float2(v.w, v.w);
        }
        #pragma unroll
        for (int t = 0; t < 2; t++) {
            int i = tid + t*256;
            int n = i >> 2, kg = (i & 3) * 4;
            float4 v = *(const float4*)&W[(size_t)(j0 + n)*64 + k0 + kg];
            Bs[kg+0][n] = v.x; Bs[kg+1][n] = v.y; Bs[kg+2][n] = v.z; Bs[kg+3][n] = v.w;
        }
        __syncthreads();
        #pragma unroll
        for (int k = 0; k < GKC; k++) {
            float4 a01 = *(const float4*)&As2[k][tr*16];
            float4 a23 = *(const float4*)&As2[k][tr*16 + 4];
            float4 a45 = *(const float4*)&As2[k][tr*16 + 8];
            float4 a67 = *(const float4*)&As2[k][tr*16 + 12];
            float4 b03 = *(const float4*)&Bs[k][tc*8];
            float4 b47 = *(const float4*)&Bs[k][tc*8 + 4];
            float2 a2[8] = { {a01.x,a01.y},{a01.z,a01.w},{a23.x,a23.y},{a23.z,a23.w},
                             {a45.x,a45.y},{a45.z,a45.w},{a67.x,a67.y},{a67.z,a67.w} };
            float2 b2[4] = { {b03.x,b03.y},{b03.z,b03.w},{b47.x,b47.y},{b47.z,b47.w} };
            #pragma unroll
            for (int ii = 0; ii < 8; ii++)
                #pragma unroll
                for (int jj = 0; jj < 4; jj++)
                    acc[ii][jj] = ffma2(a2[ii], b2[jj], acc[ii][jj]);
        }
        __syncthreads();
    }
    float* Cout = g_zx[dir];
    #pragma unroll
    for (int ii = 0; ii < 8; ii++) {
        size_t m = bm + tr*8 + ii;
        float4 o0 = make_float4(acc[ii][0].x, acc[ii][0].y, acc[ii][1].x, acc[ii][1].y);
        float4 o1 = make_float4(acc[ii][2].x, acc[ii][2].y, acc[ii][3].x, acc[ii][3].y);
        *(float4*)&Cout[m*384 + j0 + tc*8]     = o0;
        *(float4*)&Cout[m*384 + j0 + tc*8 + 4] = o1;
    }
}

// ============================================================
// dt precompute: g_dt[dir][r] = {dt0, dt1, ldA0, ldA1}, ldA = -exp(Alog)*dt
// ============================================================
__global__ __launch_bounds__(256) void dt_kernel(const float* __restrict__ inW,
        const float* __restrict__ dtb, const float* __restrict__ Alog, int pf, int pb)
{
    __shared__ float usm[128][65];
    __shared__ float wsm[2][2][64];
    __shared__ float par[2][2][2];
    int tid = threadIdx.x;
    int r0 = blockIdx.x * 128;
    for (int i = tid; i < 8192; i += 256) {
        int m = i >> 6, k = i & 63;
        usm[m][k] = g_u[(size_t)(r0 + m)*64 + k];
    }
    {
        int d = tid >> 7, rest = tid & 127, h = rest >> 6, k = rest & 63;
        int pidx = d ? pb : pf;
        wsm[d][h][k] = inW[(size_t)pidx*386*64 + (384 + h)*64 + k];
    }
    if (tid < 4) {
        int d = tid >> 1, h = tid & 1;
        int pidx = d ? pb : pf;
        par[d][h][0] = dtb[pidx*2 + h];
        par[d][h][1] = -expf(Alog[pidx*2 + h]);
    }
    __syncthreads();
    int rl = tid & 127, d = tid >> 7;
    float out[4];
    #pragma unroll
    for (int h = 0; h < 2; h++) {
        float acc = 0.f;
        #pragma unroll
        for (int k = 0; k < 64; k++) acc = fmaf(usm[rl][k], wsm[d][h][k], acc);
        float xr = acc + par[d][h][0];
        float dt = (xr > 20.f) ? xr : log1pf(expf(xr));
        out[h] = dt;
        out[2 + h] = par[d][h][1] * dt;   // log dA
    }
    float* o = &g_dt[d][(size_t)(r0 + rl)*4];
    o[0] = out[0]; o[1] = out[1]; o[2] = out[2]; o[3] = out[3];
}

// ============================================================
// Depthwise causal conv + silu, IN-PLACE on g_zx[dir][:,128:384].
// Block = (dir, seq); thread = channel; window kept in registers.
// ============================================================
__global__ __launch_bounds__(256) void conv_kernel(const float* __restrict__ convW,
        const float* __restrict__ convB, int pf, int pb)
{
    int blk = blockIdx.x, dir = blk >> 9, s = blk & 511;
    int pidx = dir ? pb : pf;
    int ch = threadIdx.x;
    float cw0 = convW[pidx*1024 + ch*4 + 0];
    float cw1 = convW[pidx*1024 + ch*4 + 1];
    float cw2 = convW[pidx*1024 + ch*4 + 2];
    float cw3 = convW[pidx*1024 + ch*4 + 3];
    float cb  = convB[pidx*256 + ch];
    float* base = g_zx[dir] + (size_t)s * L_ * 384 + 128 + ch;
    float xm3 = 0.f, xm2 = 0.f, xm1 = 0.f;

    float nxt[4];
    #pragma unroll
    for (int j = 0; j < 4; j++) {
        int lp = dir ? 127 - j : j;
        nxt[j] = base[(size_t)lp*384];
    }
    for (int l0 = 0; l0 < 128; l0 += 4) {
        float cur[4];
        #pragma unroll
        for (int j = 0; j < 4; j++) cur[j] = nxt[j];
        if (l0 + 4 < 128) {
            #pragma unroll
            for (int j = 0; j < 4; j++) {
                int l = l0 + 4 + j;
                int lp = dir ? 127 - l : l;
                nxt[j] = base[(size_t)lp*384];
            }
        }
        #pragma unroll
        for (int j = 0; j < 4; j++) {
            float v = cur[j];
            float acc = cb;
            acc = fmaf(cw0, xm3, acc);
            acc = fmaf(cw1, xm2, acc);
            acc = fmaf(cw2, xm1, acc);
            acc = fmaf(cw3, v,   acc);
            xm3 = xm2; xm2 = xm1; xm1 = v;
            float y = acc / (1.f + expf(-acc));
            int l = l0 + j;
            int lp = dir ? 127 - l : l;
            base[(size_t)lp*384] = y;
        }
    }
}

// ============================================================
// SSD kernel: per (seq, dir): P = C.B^T (shared over heads),
// per head: G = mask*dt_s*exp(LL_t-LL_s)*P ; Y = G.X ; fused
// D*x + gate(z) + rmsnorm epilogue -> g_gbuf.
// Dynamic smem layout (floats):
//   A  @ 0      : Bs[64][132] | Cs[64][132]  -> later Xs[128][132]
//   P  @ 16896  : Ps[128][132]   (P[s][t], k-major for GEMM2)
//   G  @ 33792  : Gs[128][132]
//   LL @ 50688  : [2][128] ; DT @ 50944 : [2][128]
// ============================================================
#define SM_A 0
#define SM_P 16896
#define SM_G 33792
#define SM_LL 50688
#define SM_DT 50944
#define SSD_SMEM_FLOATS 51200
#define SSD_SMEM_BYTES (SSD_SMEM_FLOATS*4)

__global__ __launch_bounds__(256, 1) void ssd_kernel(
    const float* __restrict__ Dp, const float* __restrict__ normw, int pf, int pb)
{
    extern __shared__ float sm[];
    int blk = blockIdx.x, dir = blk >> 9, s = blk & 511;
    int pidx = dir ? pb : pf;
    int tid = threadIdx.x;
    int wid = tid >> 5, lane = tid & 31;
    const float* zxa = g_zx[dir] + (size_t)s * L_ * 384;

    // ---- phase 1: load B,C (transposed, k-major) + LL scan + dt ----
    {
        int n_all = tid & 127;
        int lg = tid >> 7;
        float* dst = sm + SM_A + ((n_all < 64) ? (n_all*132) : (8448 + (n_all-64)*132));
        const float* src = zxa + 256 + n_all;
        #pragma unroll
        for (int c = 0; c < 16; c++) {
            int l0 = lg*64 + c*4;
            float4 v;
            v.x = src[(size_t)(dir ? 127-(l0+0) : (l0+0))*384];
            v.y = src[(size_t)(dir ? 127-(l0+1) : (l0+1))*384];
            v.z = src[(size_t)(dir ? 127-(l0+2) : (l0+2))*384];
            v.w = src[(size_t)(dir ? 127-(l0+3) : (l0+3))*384];
            *(float4*)&dst[l0] = v;
        }
    }
    if (wid < 2) {
        int h = wid;
        float carry = 0.f;
        for (int c = 0; c < 4; c++) {
            int l = c*32 + lane;
            int lp = dir ? 127 - l : l;
            const float* dr = g_dt[dir] + ((size_t)s*128 + lp)*4;
            sm[SM_DT + h*128 + l] = dr[h];
            float v = dr[2 + h];
            #pragma unroll
            for (int o = 1; o < 32; o <<= 1) {
                float t = __shfl_up_sync(0xffffffffu, v, o);
                if (lane >= o) v += t;
            }
            sm[SM_LL + h*128 + l] = v + carry;
            carry += __shfl_sync(0xffffffffu, v, 31);
        }
    }
    __syncthreads();

    // ---- phase 2: GEMM1: P[t][s] = sum_n C[t][n] * B[s][n] ----
    {
        int wt = wid >> 1, ws = wid & 1;
        int t0 = wt*32 + (lane >> 3)*8;
        int s0 = ws*64 + (lane & 7)*8;
        if (s0 <= t0 + 7) {
            const float* BsP = sm + SM_A;
            const float* CsP = sm + SM_A + 8448;
            float2 pacc[8][4];
            #pragma unroll
            for (int i = 0; i < 8; i++)
                #pragma unroll
                for (int j = 0; j < 4; j++) pacc[i][j] = make_float2(0.f, 0.f);
            #pragma unroll 4
            for (int n = 0; n < 64; n++) {
                float4 c03 = *(const float4*)&CsP[n*132 + t0];
                float4 c47 = *(const float4*)&CsP[n*132 + t0 + 4];
                float4 b03 = *(const float4*)&BsP[n*132 + s0];
                float4 b47 = *(const float4*)&BsP[n*132 + s0 + 4];
                float a[8] = {c03.x,c03.y,c03.z,c03.w,c47.x,c47.y,c47.z,c47.w};
                float2 bb[4] = {{b03.x,b03.y},{b03.z,b03.w},{b47.x,b47.y},{b47.z,b47.w}};
                #pragma unroll
                for (int i = 0; i < 8; i++) {
                    float2 aa = dup2(a[i]);
                    #pragma unroll
                    for (int j = 0; j < 4; j++)
                        pacc[i][j] = ffma2(aa, bb[j], pacc[i][j]);
                }
            }
            #pragma unroll
            for (int k = 0; k < 8; k++) {
                float v[8];
                #pragma unroll
                for (int i = 0; i < 8; i++)
                    v[i] = (k & 1) ? pacc[i][k>>1].y : pacc[i][k>>1].x;
                *(float4*)&sm[SM_P + (s0+k)*132 + t0]     = make_float4(v[0],v[1],v[2],v[3]);
                *(float4*)&sm[SM_P + (s0+k)*132 + t0 + 4] = make_float4(v[4],v[5],v[6],v[7]);
            }
        }
    }
    __syncthreads();

    // ---- phase 3: load X (overwrites B/C region) ----
    #pragma unroll
    for (int c = 0; c < 16; c++) {
        int i = tid + c*256;
        int l = i >> 5, q = i & 31;
        int lp = dir ? 127 - l : l;
        float4 v = *(const float4*)&zxa[(size_t)lp*384 + 128 + q*4];
        *(float4*)&sm[SM_A + l*132 + q*4] = v;
    }

    int ti = tid >> 4, pi = tid & 15, t0g = ti*8;
    float2 accY[2][8][2];

    #pragma unroll
    for (int h = 0; h < 2; h++) {
        // ---- decay/mask pass: G[s][t] = P[s][t] * dt_s * exp(LL_t - LL_s) ----
        {
            // for h==0 this also needs phase-3 X store NOT conflicting: disjoint regions
            if (h == 1) __syncthreads();   // wait GEMM2 head0 done reading G
            int sI = tid >> 1, hf = tid & 1;
            float dts = sm[SM_DT + h*128 + sI];
            float lls = sm[SM_LL + h*128 + sI];
            const float* Prow = sm + SM_P + sI*132;
            float* Grow = sm + SM_G + sI*132;
            #pragma unroll
            for (int c = 0; c < 16; c++) {
                int t = hf*64 + c*4;
                float4 p4 = *(const float4*)&Prow[t];
                float4 l4 = *(const float4*)&sm[SM_LL + h*128 + t];
                float4 g4;
                g4.x = (sI <= t+0) ? p4.x * dts * __expf(l4.x - lls) : 0.f;
                g4.y = (sI <= t+1) ? p4.y * dts * __expf(l4.y - lls) : 0.f;
                g4.z = (sI <= t+2) ? p4.z * dts * __expf(l4.z - lls) : 0.f;
                g4.w = (sI <= t+3) ? p4.w * dts * __expf(l4.w - lls) : 0.f;
                *(float4*)&Grow[t] = g4;
            }
        }
        __syncthreads();
        // ---- GEMM2: Y[t][p] = sum_s G[s][t] * X[s][h*64+p] ----
        #pragma unroll
        for (int i = 0; i < 8; i++) {
            accY[h][i][0] = make_float2(0.f, 0.f);
            accY[h][i][1] = make_float2(0.f, 0.f);
        }
        int kmax = t0g + 8;
        for (int sI = 0; sI < kmax; sI++) {
            const float* Gr = sm + SM_G + sI*132;
            float4 a03 = *(const float4*)&Gr[t0g];
            float4 a47 = *(const float4*)&Gr[t0g + 4];
            float4 bx  = *(const float4*)&sm[SM_A + sI*132 + h*64 + pi*4];
            float2 b0 = make_float2(bx.x, bx.y), b1 = make_float2(bx.z, bx.w);
            float a[8] = {a03.x,a03.y,a03.z,a03.w,a47.x,a47.y,a47.z,a47.w};
            #pragma unroll
            for (int i = 0; i < 8; i++) {
                float2 aa = dup2(a[i]);
                accY[h][i][0] = ffma2(aa, b0, accY[h][i][0]);
                accY[h][i][1] = ffma2(aa, b1, accY[h][i][1]);
            }
        }
    }

    // ---- epilogue: +D*x, gate silu(z), rmsnorm(128), *norm_w -> g_gbuf ----
    {
        float Dv0 = Dp[pidx*2], Dv1 = Dp[pidx*2 + 1];
        float4 nw0 = *(const float4*)&normw[pidx*128 + pi*4];
        float4 nw1 = *(const float4*)&normw[pidx*128 + 64 + pi*4];
        #pragma unroll
        for (int i = 0; i < 8; i++) {
            int l = t0g + i;
            int lp = dir ? 127 - l : l;
            float4 x0 = *(const float4*)&sm[SM_A + l*132 + pi*4];
            float4 x1 = *(const float4*)&sm[SM_A + l*132 + 64 + pi*4];
            const float* zr = g_zx[dir] + ((size_t)s*128 + lp)*384;
            float4 z0 = *(const float4*)&zr[pi*4];
            float4 z1 = *(const float4*)&zr[64 + pi*4];
            float g[8];
            g[0] = fmaf(Dv0, x0.x, accY[0][i][0].x);
            g[1] = fmaf(Dv0, x0.y, accY[0][i][0].y);
            g[2] = fmaf(Dv0, x0.z, accY[0][i][1].x);
            g[3] = fmaf(Dv0, x0.w, accY[0][i][1].y);
            g[4] = fmaf(Dv1, x1.x, accY[1][i][0].x);
            g[5] = fmaf(Dv1, x1.y, accY[1][i][0].y);
            g[6] = fmaf(Dv1, x1.z, accY[1][i][1].x);
            g[7] = fmaf(Dv1, x1.w, accY[1][i][1].y);
            float z[8] = {z0.x, z0.y, z0.z, z0.w, z1.x, z1.y, z1.z, z1.w};
            float ss = 0.f;
            #pragma unroll
            for (int j = 0; j < 8; j++) {
                g[j] = g[j] * (z[j] / (1.f + expf(-z[j])));
                ss = fmaf(g[j], g[j], ss);
            }
            ss += __shfl_xor_sync(0xffffffffu, ss, 1);
            ss += __shfl_xor_sync(0xffffffffu, ss, 2);
            ss += __shfl_xor_sync(0xffffffffu, ss, 4);
            ss += __shfl_xor_sync(0xffffffffu, ss, 8);
            float rs = rsqrtf(ss * 0.0078125f + 1e-5f);
            float* go = g_gbuf + ((size_t)s*128 + lp)*256 + (dir << 7);
            *(float4*)&go[pi*4]      = make_float4(g[0]*rs*nw0.x, g[1]*rs*nw0.y,
                                                   g[2]*rs*nw0.z, g[3]*rs*nw0.w);
            *(float4*)&go[64 + pi*4] = make_float4(g[4]*rs*nw1.x, g[5]*rs*nw1.y,
                                                   g[6]*rs*nw1.z, g[7]*rs*nw1.w);
        }
    }
}

// ============================================================
// Fold out_proj x fusion
// ============================================================
__global__ void wc_kernel(const float* __restrict__ fW, const float* __restrict__ oW,
                          int pf, int pb)
{
    int idx = blockIdx.x*256 + threadIdx.x;
    int m = idx >> 8, r = idx & 255, dir = r >> 7, j = r & 127;
    int pidx = dir ? pb : pf;
    const float* wo = oW + (size_t)pidx*64*128;
    const float* wf = fW + m*128 + (dir << 6);
    float acc = 0.f;
    #pragma unroll
    for (int i = 0; i < 64; i++) acc = fmaf(wf[i], wo[i*128 + j], acc);
    g_wc[idx] = acc;
}

// ============================================================
// final GEMM + residual + scatter. M=65536, N=64, K=256.
// ============================================================
__global__ __launch_bounds__(256) void gemm_out(const float* __restrict__ fb,
        const float* __restrict__ x_ext, float* __restrict__ out_ext, int stage)
{
    __shared__ __align__(16) float As[16][68];
    __shared__ __align__(16) float Ws[16][68];
    const float* xin = stage ? g_xwork : x_ext;
    float* xout = stage ? out_ext : g_xwork;
    size_t bm = (size_t)blockIdx.x * 64;
    int tid = threadIdx.x, tr = tid >> 4, tc = tid & 15;
    float acc[4][4] = {};
    for (int k0 = 0; k0 < 256; k0 += 16) {
        #pragma unroll
        for (int i = tid; i < 1024; i += 256) {
            int m = i >> 4, k = i & 15;
            As[k][m] = g_gbuf[(bm + m)*256 + k0 + k];
        }
        #pragma unroll
        for (int i = tid; i < 1024; i += 256) {
            int n = i >> 4, k = i & 15;
            Ws[k][n] = g_wc[n*256 + k0 + k];
        }
        __syncthreads();
        #pragma unroll
        for (int k = 0; k < 16; k++) {
            float a[4], b4[4];
            *(float4*)a  = *(const float4*)&As[k][tr*4];
            *(float4*)b4 = *(const float4*)&Ws[k][tc*4];
            #pragma unroll
            for (int ii = 0; ii < 4; ii++)
                #pragma unroll
                for (int jj = 0; jj < 4; jj++)
                    acc[ii][jj] = fmaf(a[ii], b4[jj], acc[ii][jj]);
        }
        __syncthreads();
    }
    #pragma unroll
    for (int ii = 0; ii < 4; ii++) {
        size_t r = bm + tr*4 + ii;
        int b = (int)(r >> 14), low = (int)(r & 16383);
        int t_, f_;
        if (stage == 0) { t_ = low >> 7; f_ = low & 127; }
        else            { f_ = low >> 7; t_ = low & 127; }
        #pragma unroll
        for (int jj = 0; jj < 4; jj++) {
            int n = tc*4 + jj;
            size_t idx = (((size_t)(b*64 + n)*128) + t_)*128 + f_;
            xout[idx] = xin[idx] + acc[ii][jj] + fb[n];
        }
    }
}

// ============================================================
extern "C" void kernel_launch(void* const* d_in, const int* in_sizes, int n_in,
                              void* d_out, int out_size)
{
    const float* x     = (const float*)d_in[0];
    const float* inW   = (const float*)d_in[1];
    const float* convW = (const float*)d_in[2];
    const float* convB = (const float*)d_in[3];
    const float* dtb   = (const float*)d_in[4];
    const float* Alog  = (const float*)d_in[5];
    const float* Dp    = (const float*)d_in[6];
    const float* nw    = (const float*)d_in[7];
    const float* outW  = (const float*)d_in[8];
    const float* fW    = (const float*)d_in[9];
    const float* fb    = (const float*)d_in[10];
    const float* lnw   = (const float*)d_in[11];
    const float* lnb   = (const float*)d_in[12];
    float* out = (float*)d_out;

    cudaFuncSetAttribute(ssd_kernel, cudaFuncAttributeMaxDynamicSharedMemorySize,
                         SSD_SMEM_BYTES);

    for (int st = 0; st < 2; st++) {
        int pf = 2*st, pb = 2*st + 1;
        ln_kernel<<<512, 256>>>(x, lnw + st*64, lnb + st*64, st);
        gemm_in<<<dim3(6, 512), 256>>>(inW + (size_t)pf*386*64, inW + (size_t)pb*386*64);
        dt_kernel<<<512, 256>>>(inW, dtb, Alog, pf, pb);
        conv_kernel<<<1024, 256>>>(convW, convB, pf, pb);
        ssd_kernel<<<1024, 256, SSD_SMEM_BYTES>>>(Dp, nw, pf, pb);
        wc_kernel<<<64, 256>>>(fW + st*64*128, outW, pf, pb);
        gemm_out<<<1024, 256>>>(fb + st*64, x, out, st);
    }
}

// round 5
// speedup vs baseline: 1.3334x; 1.1572x over previous
#include <cuda_runtime.h>
#include <math.h>

#define S_ 512
#define L_ 128

// ---- packed f32x2 helpers ----
__device__ __forceinline__ float2 ffma2(float2 a, float2 b, float2 c) {
    unsigned long long ua = *reinterpret_cast<unsigned long long*>(&a);
    unsigned long long ub = *reinterpret_cast<unsigned long long*>(&b);
    unsigned long long uc = *reinterpret_cast<unsigned long long*>(&c);
    unsigned long long ud;
    asm("fma.rn.f32x2 %0, %1, %2, %3;" : "=l"(ud) : "l"(ua), "l"(ub), "l"(uc));
    return *reinterpret_cast<float2*>(&ud);
}
__device__ __forceinline__ float2 dup2(float a) {
    unsigned long long u;
    asm("mov.b64 %0, {%1, %1};" : "=l"(u) : "f"(a));
    return *reinterpret_cast<float2*>(&u);
}

// ---- scratch ----
__device__ __align__(16) float g_xwork[(size_t)4*64*128*128];
__device__ __align__(16) float g_u[(size_t)S_*L_*64];
__device__ __align__(16) float g_zx[2][(size_t)S_*L_*384];   // z | raw xBC
__device__ __align__(16) float g_dt[2][(size_t)S_*L_*4];     // {dt0,dt1,ldA0,ldA1}
__device__ __align__(16) float g_gbuf[(size_t)S_*L_*256];
__device__ __align__(16) float g_wc[64*256];

// ============================================================
// LayerNorm over channels + layout to (seq, pos, ch)
// ============================================================
__global__ void ln_kernel(const float* __restrict__ x_ext,
                          const float* __restrict__ lnw, const float* __restrict__ lnb,
                          int stage)
{
    __shared__ float tile[64][133];
    __shared__ float msh[128], rsh[128], wsh[64], bsh[64];
    const float* xin = stage ? g_xwork : x_ext;
    int bt = blockIdx.x, b = bt >> 7, t = bt & 127;
    int tid = threadIdx.x;
    if (tid < 64) { wsh[tid] = lnw[tid]; bsh[tid] = lnb[tid]; }
    const float* xb = xin + ((size_t)b*64*128 + t)*128;
    for (int i = tid; i < 8192; i += 256) {
        int c = i >> 7, f = i & 127;
        tile[c][f] = xb[(size_t)c*16384 + f];
    }
    __syncthreads();
    if (tid < 128) {
        float s = 0.f, ss = 0.f;
        #pragma unroll
        for (int c = 0; c < 64; c++) { float v = tile[c][tid]; s += v; ss += v*v; }
        float m = s * 0.015625f;
        msh[tid] = m;
        rsh[tid] = rsqrtf(ss * 0.015625f - m*m + 1e-5f);
    }
    __syncthreads();
    for (int i = tid; i < 8192; i += 256) {
        int f = i >> 6, c = i & 63;
        int row = stage ? ((b << 7) + f)*128 + t : ((b << 7) + t)*128 + f;
        g_u[(size_t)row*64 + c] = (tile[c][f] - msh[f]) * rsh[f] * wsh[c] + bsh[c];
    }
}

// ============================================================
// in_proj GEMM, both directions. M=65536, N=768, K=64.
// ============================================================
#define GKC 16
__global__ __launch_bounds__(256, 2) void gemm_in(const float* __restrict__ Wf,
                                                  const float* __restrict__ Wb)
{
    __shared__ __align__(16) float As2[GKC][264];
    __shared__ __align__(16) float Bs[GKC][132];
    int bx = blockIdx.x;
    int dir = (bx >= 3);
    const float* W = dir ? Wb : Wf;
    int j0 = (bx - dir*3) * 128;
    size_t bm = (size_t)blockIdx.y * 128;
    int tid = threadIdx.x;
    int tr = tid >> 4, tc = tid & 15;
    float2 acc[8][4];
    #pragma unroll
    for (int i = 0; i < 8; i++)
        #pragma unroll
        for (int j = 0; j < 4; j++) acc[i][j] = make_float2(0.f, 0.f);

    for (int k0 = 0; k0 < 64; k0 += GKC) {
        #pragma unroll
        for (int t = 0; t < 2; t++) {
            int i = tid + t*256;
            int m = i >> 2, kg = (i & 3) * 4;
            float4 v = *(const float4*)&g_u[(bm + m)*64 + k0 + kg];
            *(float2*)&As2[kg+0][2*m] = make_float2(v.x, v.x);
            *(float2*)&As2[kg+1][2*m] = make_float2(v.y, v.y);
            *(float2*)&As2[kg+2][2*m] = make_float2(v.z, v.z);
            *(float2*)&As2[kg+3][2*m] = make_float2(v.w, v.w);
        }
        #pragma unroll
        for (int t = 0; t < 2; t++) {
            int i = tid + t*256;
            int n = i >> 2, kg = (i & 3) * 4;
            float4 v = *(const float4*)&W[(size_t)(j0 + n)*64 + k0 + kg];
            Bs[kg+0][n] = v.x; Bs[kg+1][n] = v.y; Bs[kg+2][n] = v.z; Bs[kg+3][n] = v.w;
        }
        __syncthreads();
        #pragma unroll
        for (int k = 0; k < GKC; k++) {
            float4 a01 = *(const float4*)&As2[k][tr*16];
            float4 a23 = *(const float4*)&As2[k][tr*16 + 4];
            float4 a45 = *(const float4*)&As2[k][tr*16 + 8];
            float4 a67 = *(const float4*)&As2[k][tr*16 + 12];
            float4 b03 = *(const float4*)&Bs[k][tc*8];
            float4 b47 = *(const float4*)&Bs[k][tc*8 + 4];
            float2 a2[8] = { {a01.x,a01.y},{a01.z,a01.w},{a23.x,a23.y},{a23.z,a23.w},
                             {a45.x,a45.y},{a45.z,a45.w},{a67.x,a67.y},{a67.z,a67.w} };
            float2 b2[4] = { {b03.x,b03.y},{b03.z,b03.w},{b47.x,b47.y},{b47.z,b47.w} };
            #pragma unroll
            for (int ii = 0; ii < 8; ii++)
                #pragma unroll
                for (int jj = 0; jj < 4; jj++)
                    acc[ii][jj] = ffma2(a2[ii], b2[jj], acc[ii][jj]);
        }
        __syncthreads();
    }
    float* Cout = g_zx[dir];
    #pragma unroll
    for (int ii = 0; ii < 8; ii++) {
        size_t m = bm + tr*8 + ii;
        float4 o0 = make_float4(acc[ii][0].x, acc[ii][0].y, acc[ii][1].x, acc[ii][1].y);
        float4 o1 = make_float4(acc[ii][2].x, acc[ii][2].y, acc[ii][3].x, acc[ii][3].y);
        *(float4*)&Cout[m*384 + j0 + tc*8]     = o0;
        *(float4*)&Cout[m*384 + j0 + tc*8 + 4] = o1;
    }
}

// ============================================================
// dt precompute: g_dt[dir][r] = {dt0, dt1, ldA0, ldA1}, ldA = -exp(Alog)*dt
// ============================================================
__global__ __launch_bounds__(256) void dt_kernel(const float* __restrict__ inW,
        const float* __restrict__ dtb, const float* __restrict__ Alog, int pf, int pb)
{
    __shared__ float usm[128][65];
    __shared__ float wsm[2][2][64];
    __shared__ float par[2][2][2];
    int tid = threadIdx.x;
    int r0 = blockIdx.x * 128;
    for (int i = tid; i < 8192; i += 256) {
        int m = i >> 6, k = i & 63;
        usm[m][k] = g_u[(size_t)(r0 + m)*64 + k];
    }
    {
        int d = tid >> 7, rest = tid & 127, h = rest >> 6, k = rest & 63;
        int pidx = d ? pb : pf;
        wsm[d][h][k] = inW[(size_t)pidx*386*64 + (384 + h)*64 + k];
    }
    if (tid < 4) {
        int d = tid >> 1, h = tid & 1;
        int pidx = d ? pb : pf;
        par[d][h][0] = dtb[pidx*2 + h];
        par[d][h][1] = -expf(Alog[pidx*2 + h]);
    }
    __syncthreads();
    int rl = tid & 127, d = tid >> 7;
    float out[4];
    #pragma unroll
    for (int h = 0; h < 2; h++) {
        float acc = 0.f;
        #pragma unroll
        for (int k = 0; k < 64; k++) acc = fmaf(usm[rl][k], wsm[d][h][k], acc);
        float xr = acc + par[d][h][0];
        float dt = (xr > 20.f) ? xr : log1pf(expf(xr));
        out[h] = dt;
        out[2 + h] = par[d][h][1] * dt;   // log dA
    }
    float* o = &g_dt[d][(size_t)(r0 + rl)*4];
    o[0] = out[0]; o[1] = out[1]; o[2] = out[2]; o[3] = out[3];
}

// ============================================================
// Fused SSD: conv+silu (in-block) -> GEMM1(C.B^T)+decay (fused, s-panels)
// -> GEMM2 (triangular) -> D*x + gate + rmsnorm epilogue.
// 512 threads, one block per (seq, dir).
// smem (floats):
//   X  @ 0     : [128 l][132]  conv'd x
//   BT @ 16896 : [64 n][132]   conv'd B^T
//   CT @ 25344 : [64 n][132]   conv'd C^T
//   G  @ 33792 : [2 h][64 s][132]  per-panel decayed scores
//   LL @ 50688 : [2][128] ; DT @ 50944 : [2][128]
// ============================================================
#define SMX 0
#define SMBT 16896
#define SMCT 25344
#define SMG 33792
#define SMLL 50688
#define SMDT 50944
#define SSD_SMEM_FLOATS 51200
#define SSD_SMEM_BYTES (SSD_SMEM_FLOATS*4)

__global__ __launch_bounds__(512, 1) void ssd_kernel(
    const float* __restrict__ convW, const float* __restrict__ convB,
    const float* __restrict__ Dp, const float* __restrict__ normw, int pf, int pb)
{
    extern __shared__ float sm[];
    int blk = blockIdx.x, dir = blk >> 9, s = blk & 511;
    int pidx = dir ? pb : pf;
    int tid = threadIdx.x;
    const float* zxa = g_zx[dir] + (size_t)s * L_ * 384;

    // ---- phase 0: depthwise conv(k=4, causal in logical order) + silu,
    //      written transposed into smem. 512 thr = 256 ch x 2 l-halves.
    {
        int ch = tid & 255, hf = tid >> 8;
        float cw0 = convW[pidx*1024 + ch*4 + 0];
        float cw1 = convW[pidx*1024 + ch*4 + 1];
        float cw2 = convW[pidx*1024 + ch*4 + 2];
        float cw3 = convW[pidx*1024 + ch*4 + 3];
        float cb  = convB[pidx*256 + ch];
        const float* src = zxa + 128 + ch;
        float* obase;
        int ostep;
        if (ch < 128)      { obase = sm + SMX + ch;              ostep = 132; }
        else if (ch < 192) { obase = sm + SMBT + (ch-128)*132;   ostep = 1;   }
        else               { obase = sm + SMCT + (ch-192)*132;   ostep = 1;   }
        int ls = hf * 64;
        float xm3 = 0.f, xm2 = 0.f, xm1 = 0.f;
        #pragma unroll
        for (int j = 0; j < 3; j++) {
            int l = ls - 3 + j;
            float v = 0.f;
            if (l >= 0) v = src[(size_t)(dir ? 127-l : l)*384];
            xm3 = xm2; xm2 = xm1; xm1 = v;
        }
        float nxt[4];
        #pragma unroll
        for (int j = 0; j < 4; j++)
            nxt[j] = src[(size_t)(dir ? 127-(ls+j) : (ls+j))*384];
        for (int lb = 0; lb < 64; lb += 4) {
            float cur[4];
            #pragma unroll
            for (int j = 0; j < 4; j++) cur[j] = nxt[j];
            if (lb + 4 < 64) {
                #pragma unroll
                for (int j = 0; j < 4; j++) {
                    int l = ls + lb + 4 + j;
                    nxt[j] = src[(size_t)(dir ? 127-l : l)*384];
                }
            }
            #pragma unroll
            for (int j = 0; j < 4; j++) {
                float v = cur[j];
                float acc = cb;
                acc = fmaf(cw0, xm3, acc);
                acc = fmaf(cw1, xm2, acc);
                acc = fmaf(cw2, xm1, acc);
                acc = fmaf(cw3, v,   acc);
                xm3 = xm2; xm2 = xm1; xm1 = v;
                float y = acc / (1.f + expf(-acc));
                obase[(ls + lb + j) * ostep] = y;
            }
        }
    }
    // ---- LL prefix scan + dt (warps 0,1) ----
    if (tid < 64) {
        int h = tid >> 5, lane = tid & 31;
        float carry = 0.f;
        for (int c = 0; c < 4; c++) {
            int l = c*32 + lane;
            int lp = dir ? 127 - l : l;
            const float* dr = g_dt[dir] + ((size_t)s*128 + lp)*4;
            sm[SMDT + h*128 + l] = dr[h];
            float v = dr[2 + h];
            #pragma unroll
            for (int o = 1; o < 32; o <<= 1) {
                float t = __shfl_up_sync(0xffffffffu, v, o);
                if (lane >= o) v += t;
            }
            sm[SMLL + h*128 + l] = v + carry;
            carry += __shfl_sync(0xffffffffu, v, 31);
        }
    }
    __syncthreads();

    int ti = tid >> 4;          // 0..31 (4 t-rows each)
    int pi = tid & 15;
    int t0 = ti * 4;
    float2 accY[2][4][2];
    #pragma unroll
    for (int h = 0; h < 2; h++)
        #pragma unroll
        for (int i = 0; i < 4; i++) {
            accY[h][i][0] = make_float2(0.f, 0.f);
            accY[h][i][1] = make_float2(0.f, 0.f);
        }

    #pragma unroll
    for (int p = 0; p < 2; p++) {
        int s_base = p * 64;
        int s0 = s_base + pi * 4;
        // ---- GEMM1: pacc[t 4][s 4] = sum_n C[t][n]*B[s][n] ----
        float2 pacc[4][2];
        #pragma unroll
        for (int i = 0; i < 4; i++) {
            pacc[i][0] = make_float2(0.f, 0.f);
            pacc[i][1] = make_float2(0.f, 0.f);
        }
        if (s0 <= t0 + 3) {
            #pragma unroll 4
            for (int n = 0; n < 64; n++) {
                float4 c4 = *(const float4*)&sm[SMCT + n*132 + t0];
                float4 b4 = *(const float4*)&sm[SMBT + n*132 + s0];
                float a[4] = {c4.x, c4.y, c4.z, c4.w};
                float2 bb[2] = {{b4.x, b4.y}, {b4.z, b4.w}};
                #pragma unroll
                for (int i = 0; i < 4; i++) {
                    float2 aa = dup2(a[i]);
                    pacc[i][0] = ffma2(aa, bb[0], pacc[i][0]);
                    pacc[i][1] = ffma2(aa, bb[1], pacc[i][1]);
                }
            }
        }
        // ---- fused decay: G[h][s-s_base][t] = pacc*dt_s*exp(ll_t-ll_s), s<=t ----
        #pragma unroll
        for (int h = 0; h < 2; h++) {
            float llt[4];
            #pragma unroll
            for (int i = 0; i < 4; i++) llt[i] = sm[SMLL + h*128 + t0 + i];
            #pragma unroll
            for (int j = 0; j < 4; j++) {
                int sg = s0 + j;
                float dts = sm[SMDT + h*128 + sg];
                float lls = sm[SMLL + h*128 + sg];
                float pv[4];
                #pragma unroll
                for (int i = 0; i < 4; i++)
                    pv[i] = (j & 1) ? pacc[i][j>>1].y : pacc[i][j>>1].x;
                float4 g4;
                g4.x = (sg <= t0+0) ? pv[0]*dts*__expf(llt[0]-lls) : 0.f;
                g4.y = (sg <= t0+1) ? pv[1]*dts*__expf(llt[1]-lls) : 0.f;
                g4.z = (sg <= t0+2) ? pv[2]*dts*__expf(llt[2]-lls) : 0.f;
                g4.w = (sg <= t0+3) ? pv[3]*dts*__expf(llt[3]-lls) : 0.f;
                *(float4*)&sm[SMG + (h*64 + sg - s_base)*132 + t0] = g4;
            }
        }
        __syncthreads();
        // ---- GEMM2 partial: Y[t][p] += sum_{s in panel} G[s][t]*X[s][p] ----
        int klim = t0 + 4 - s_base;
        if (klim > 64) klim = 64;
        for (int sl = 0; sl < klim; sl++) {
            int sg = s_base + sl;
            float4 g0 = *(const float4*)&sm[SMG + sl*132 + t0];
            float4 g1 = *(const float4*)&sm[SMG + (64 + sl)*132 + t0];
            float4 x0 = *(const float4*)&sm[SMX + sg*132 + pi*4];
            float4 x1 = *(const float4*)&sm[SMX + sg*132 + 64 + pi*4];
            float2 b00 = {x0.x, x0.y}, b01 = {x0.z, x0.w};
            float2 b10 = {x1.x, x1.y}, b11 = {x1.z, x1.w};
            float ga0[4] = {g0.x, g0.y, g0.z, g0.w};
            float ga1[4] = {g1.x, g1.y, g1.z, g1.w};
            #pragma unroll
            for (int i = 0; i < 4; i++) {
                float2 a0 = dup2(ga0[i]);
                float2 a1 = dup2(ga1[i]);
                accY[0][i][0] = ffma2(a0, b00, accY[0][i][0]);
                accY[0][i][1] = ffma2(a0, b01, accY[0][i][1]);
                accY[1][i][0] = ffma2(a1, b10, accY[1][i][0]);
                accY[1][i][1] = ffma2(a1, b11, accY[1][i][1]);
            }
        }
        __syncthreads();
    }

    // ---- epilogue: +D*x, gate silu(z), rmsnorm(128), *norm_w -> g_gbuf ----
    {
        float Dv0 = Dp[pidx*2], Dv1 = Dp[pidx*2 + 1];
        float4 nw0 = *(const float4*)&normw[pidx*128 + pi*4];
        float4 nw1 = *(const float4*)&normw[pidx*128 + 64 + pi*4];
        #pragma unroll
        for (int i = 0; i < 4; i++) {
            int l = t0 + i;
            int lp = dir ? 127 - l : l;
            float4 x0 = *(const float4*)&sm[SMX + l*132 + pi*4];
            float4 x1 = *(const float4*)&sm[SMX + l*132 + 64 + pi*4];
            const float* zr = zxa + (size_t)lp*384;
            float4 z0 = *(const float4*)&zr[pi*4];
            float4 z1 = *(const float4*)&zr[64 + pi*4];
            float g[8];
            g[0] = fmaf(Dv0, x0.x, accY[0][i][0].x);
            g[1] = fmaf(Dv0, x0.y, accY[0][i][0].y);
            g[2] = fmaf(Dv0, x0.z, accY[0][i][1].x);
            g[3] = fmaf(Dv0, x0.w, accY[0][i][1].y);
            g[4] = fmaf(Dv1, x1.x, accY[1][i][0].x);
            g[5] = fmaf(Dv1, x1.y, accY[1][i][0].y);
            g[6] = fmaf(Dv1, x1.z, accY[1][i][1].x);
            g[7] = fmaf(Dv1, x1.w, accY[1][i][1].y);
            float z[8] = {z0.x, z0.y, z0.z, z0.w, z1.x, z1.y, z1.z, z1.w};
            float ss = 0.f;
            #pragma unroll
            for (int j = 0; j < 8; j++) {
                g[j] = g[j] * (z[j] / (1.f + expf(-z[j])));
                ss = fmaf(g[j], g[j], ss);
            }
            ss += __shfl_xor_sync(0xffffffffu, ss, 1);
            ss += __shfl_xor_sync(0xffffffffu, ss, 2);
            ss += __shfl_xor_sync(0xffffffffu, ss, 4);
            ss += __shfl_xor_sync(0xffffffffu, ss, 8);
            float rs = rsqrtf(ss * 0.0078125f + 1e-5f);
            float* go = g_gbuf + ((size_t)s*128 + lp)*256 + (dir << 7);
            *(float4*)&go[pi*4]      = make_float4(g[0]*rs*nw0.x, g[1]*rs*nw0.y,
                                                   g[2]*rs*nw0.z, g[3]*rs*nw0.w);
            *(float4*)&go[64 + pi*4] = make_float4(g[4]*rs*nw1.x, g[5]*rs*nw1.y,
                                                   g[6]*rs*nw1.z, g[7]*rs*nw1.w);
        }
    }
}

// ============================================================
// Fold out_proj x fusion
// ============================================================
__global__ void wc_kernel(const float* __restrict__ fW, const float* __restrict__ oW,
                          int pf, int pb)
{
    int idx = blockIdx.x*256 + threadIdx.x;
    int m = idx >> 8, r = idx & 255, dir = r >> 7, j = r & 127;
    int pidx = dir ? pb : pf;
    const float* wo = oW + (size_t)pidx*64*128;
    const float* wf = fW + m*128 + (dir << 6);
    float acc = 0.f;
    #pragma unroll
    for (int i = 0; i < 64; i++) acc = fmaf(wf[i], wo[i*128 + j], acc);
    g_wc[idx] = acc;
}

// ============================================================
// final GEMM + residual + scatter. M=65536, N=64, K=256.
// ============================================================
__global__ __launch_bounds__(256) void gemm_out(const float* __restrict__ fb,
        const float* __restrict__ x_ext, float* __restrict__ out_ext, int stage)
{
    __shared__ __align__(16) float As[16][68];
    __shared__ __align__(16) float Ws[16][68];
    const float* xin = stage ? g_xwork : x_ext;
    float* xout = stage ? out_ext : g_xwork;
    size_t bm = (size_t)blockIdx.x * 64;
    int tid = threadIdx.x, tr = tid >> 4, tc = tid & 15;
    float acc[4][4] = {};
    for (int k0 = 0; k0 < 256; k0 += 16) {
        #pragma unroll
        for (int i = tid; i < 1024; i += 256) {
            int m = i >> 4, k = i & 15;
            As[k][m] = g_gbuf[(bm + m)*256 + k0 + k];
        }
        #pragma unroll
        for (int i = tid; i < 1024; i += 256) {
            int n = i >> 4, k = i & 15;
            Ws[k][n] = g_wc[n*256 + k0 + k];
        }
        __syncthreads();
        #pragma unroll
        for (int k = 0; k < 16; k++) {
            float a[4], b4[4];
            *(float4*)a  = *(const float4*)&As[k][tr*4];
            *(float4*)b4 = *(const float4*)&Ws[k][tc*4];
            #pragma unroll
            for (int ii = 0; ii < 4; ii++)
                #pragma unroll
                for (int jj = 0; jj < 4; jj++)
                    acc[ii][jj] = fmaf(a[ii], b4[jj], acc[ii][jj]);
        }
        __syncthreads();
    }
    #pragma unroll
    for (int ii = 0; ii < 4; ii++) {
        size_t r = bm + tr*4 + ii;
        int b = (int)(r >> 14), low = (int)(r & 16383);
        int t_, f_;
        if (stage == 0) { t_ = low >> 7; f_ = low & 127; }
        else            { f_ = low >> 7; t_ = low & 127; }
        #pragma unroll
        for (int jj = 0; jj < 4; jj++) {
            int n = tc*4 + jj;
            size_t idx = (((size_t)(b*64 + n)*128) + t_)*128 + f_;
            xout[idx] = xin[idx] + acc[ii][jj] + fb[n];
        }
    }
}

// ============================================================
extern "C" void kernel_launch(void* const* d_in, const int* in_sizes, int n_in,
                              void* d_out, int out_size)
{
    const float* x     = (const float*)d_in[0];
    const float* inW   = (const float*)d_in[1];
    const float* convW = (const float*)d_in[2];
    const float* convB = (const float*)d_in[3];
    const float* dtb   = (const float*)d_in[4];
    const float* Alog  = (const float*)d_in[5];
    const float* Dp    = (const float*)d_in[6];
    const float* nw    = (const float*)d_in[7];
    const float* outW  = (const float*)d_in[8];
    const float* fW    = (const float*)d_in[9];
    const float* fb    = (const float*)d_in[10];
    const float* lnw   = (const float*)d_in[11];
    const float* lnb   = (const float*)d_in[12];
    float* out = (float*)d_out;

    cudaFuncSetAttribute(ssd_kernel, cudaFuncAttributeMaxDynamicSharedMemorySize,
                         SSD_SMEM_BYTES);

    for (int st = 0; st < 2; st++) {
        int pf = 2*st, pb = 2*st + 1;
        ln_kernel<<<512, 256>>>(x, lnw + st*64, lnb + st*64, st);
        gemm_in<<<dim3(6, 512), 256>>>(inW + (size_t)pf*386*64, inW + (size_t)pb*386*64);
        dt_kernel<<<512, 256>>>(inW, dtb, Alog, pf, pb);
        ssd_kernel<<<1024, 512, SSD_SMEM_BYTES>>>(convW, convB, Dp, nw, pf, pb);
        wc_kernel<<<64, 256>>>(fW + st*64*128, outW, pf, pb);
        gemm_out<<<1024, 256>>>(fb + st*64, x, out, st);
    }
}